// round 7
// baseline (speedup 1.0000x reference)
#include <cuda_runtime.h>

// ROIAlign: features (4, 64, 38, 38) fp32, rois (4, 2904, 4) -> (11616, 64, 7, 7).
//
// R7 = R6 (NHWC gathers, single-barrier smem staging, coalesced float4 flush)
// + bilinear weights/offsets hoisted into a precompute kernel (computed once
// per (roi,pixel) instead of 16x redundantly in the main kernel). The 18.2 MB
// weight/offset table is a __device__ global, L2-resident when the main
// kernel reads it back.

#define FB 4
#define FH 38
#define FW 38
#define FC 64
#define OS 7
#define PLANE (FH * FW)               // 1444
#define PER_ROI (FC * OS * OS)        // 3136
#define HALF_CH 32
#define HALF_OUT (HALF_CH * OS * OS)  // 1568
#define NPIX (OS * OS)                // 49
#define MAX_ITEMS (11616 * NPIX)      // 569184

__device__ float g_nhwc[FB * PLANE * FC];   // [b][h][w][c], 1.48 MB
__device__ float4 g_w[MAX_ITEMS];           // bilinear weights, 9.1 MB
__device__ int4   g_o[MAX_ITEMS];           // corner offsets,   9.1 MB

// ---------------- kernel 1: NCHW -> NHWC tiled transpose ----------------
__global__ __launch_bounds__(256)
void nchw2nhwc_kernel(const float* __restrict__ feat)
{
    __shared__ float tile[32][33];
    const int b = blockIdx.z;
    const int hw0 = blockIdx.x * 32;
    const int c0 = blockIdx.y * 32;

    const float* in = feat + (size_t)b * FC * PLANE;
    float* outp = g_nhwc + (size_t)b * PLANE * FC;

    const int tx = threadIdx.x;
    const int ty = threadIdx.y;

#pragma unroll
    for (int i = 0; i < 32; i += 8) {
        const int c = c0 + ty + i;
        const int hw = hw0 + tx;
        if (hw < PLANE)
            tile[ty + i][tx] = in[c * PLANE + hw];
    }
    __syncthreads();
#pragma unroll
    for (int i = 0; i < 32; i += 8) {
        const int hw = hw0 + ty + i;
        const int c = c0 + tx;
        if (hw < PLANE)
            outp[hw * FC + c] = tile[tx][ty + i];
    }
}

// ------------- kernel 2: per-(roi,pixel) weights/offsets -------------
__global__ __launch_bounds__(256)
void precompute_kernel(const float* __restrict__ rois, int n_items)
{
    const int item = blockIdx.x * 256 + threadIdx.x;
    if (item >= n_items) return;

    const int n = item / NPIX;
    const int p = item - n * NPIX;

    const float4 r = __ldg(reinterpret_cast<const float4*>(rois) + n);
    const float rw = fmaxf(r.z - r.x, 1.0f);
    const float rh = fmaxf(r.w - r.y, 1.0f);

    const int ox = p % OS;
    const int oy = p / OS;

    const float x = fmaf((float)ox * (1.0f / 6.0f), rw, r.x);
    const float y = fmaf((float)oy * (1.0f / 6.0f), rh, r.y);

    const float x0f = floorf(x);
    const float y0f = floorf(y);
    const float fx = x - x0f;
    const float fy = y - y0f;

    const int x0 = (int)x0f, y0 = (int)y0f;
    const int x1 = x0 + 1, y1 = y0 + 1;

    const bool vx0 = (x0 >= 0) && (x0 <= FW - 1);
    const bool vx1 = (x1 >= 0) && (x1 <= FW - 1);
    const bool vy0 = (y0 >= 0) && (y0 <= FH - 1);
    const bool vy1 = (y1 >= 0) && (y1 <= FH - 1);

    const int xi0 = min(max(x0, 0), FW - 1);
    const int xi1 = min(max(x1, 0), FW - 1);
    const int yi0 = min(max(y0, 0), FH - 1);
    const int yi1 = min(max(y1, 0), FH - 1);

    const float wx0 = 1.0f - fx, wx1 = fx;
    const float wy0 = 1.0f - fy, wy1 = fy;

    float4 w;
    w.x = (vx0 && vy0) ? wx0 * wy0 : 0.0f;
    w.y = (vx1 && vy0) ? wx1 * wy0 : 0.0f;
    w.z = (vx0 && vy1) ? wx0 * wy1 : 0.0f;
    w.w = (vx1 && vy1) ? wx1 * wy1 : 0.0f;
    g_w[item] = w;

    int4 o;
    o.x = (yi0 * FW + xi0) * FC;
    o.y = (yi0 * FW + xi1) * FC;
    o.z = (yi1 * FW + xi0) * FC;
    o.w = (yi1 * FW + xi1) * FC;
    g_o[item] = o;
}

// ---------------- kernel 3: ROIAlign main ----------------
// grid = (n_roi, 2). blockDim = (8, 49) = 392 threads.
__global__ __launch_bounds__(392, 5)
void roialign_nhwc_kernel(float* __restrict__ out, int nb_per_batch)
{
    __shared__ float s[HALF_OUT];        // staging: [c_local*49 + p], 6.3 KB

    const int n = blockIdx.x;
    const int half = blockIdx.y;
    const int cg = threadIdx.x;          // 0..7
    const int p = threadIdx.y;           // 0..48
    const int tid = cg + 8 * p;          // 0..391
    const int b = n / nb_per_batch;

    const int item = n * NPIX + p;
    const float4 w = __ldg(&g_w[item]);  // 8 lanes broadcast per 16B
    const int4 o = __ldg(&g_o[item]);

    // ---- gather (coalesced 128B runs across cg) + blend ----
    const float* __restrict__ fb =
        g_nhwc + (size_t)b * PLANE * FC + HALF_CH * half + 4 * cg;

    const float4 v00 = *reinterpret_cast<const float4*>(fb + o.x);
    const float4 v01 = *reinterpret_cast<const float4*>(fb + o.y);
    const float4 v10 = *reinterpret_cast<const float4*>(fb + o.z);
    const float4 v11 = *reinterpret_cast<const float4*>(fb + o.w);

    float4 a;
    a.x = fmaf(w.x, v00.x, fmaf(w.y, v01.x, fmaf(w.z, v10.x, w.w * v11.x)));
    a.y = fmaf(w.x, v00.y, fmaf(w.y, v01.y, fmaf(w.z, v10.y, w.w * v11.y)));
    a.z = fmaf(w.x, v00.z, fmaf(w.y, v01.z, fmaf(w.z, v10.z, w.w * v11.z)));
    a.w = fmaf(w.x, v00.w, fmaf(w.y, v01.w, fmaf(w.z, v10.w, w.w * v11.w)));

    // ---- stage: conflict-free STS (banks (4cg+17j+p) mod 32 all distinct) ----
    const int cl = 4 * cg;               // local channel 0..31
    s[(cl + 0) * NPIX + p] = a.x;
    s[(cl + 1) * NPIX + p] = a.y;
    s[(cl + 2) * NPIX + p] = a.z;
    s[(cl + 3) * NPIX + p] = a.w;

    __syncthreads();                     // the ONLY barrier

    // ---- flush: 392 coalesced float4 stores ----
    float4* o4 = reinterpret_cast<float4*>(
        out + (size_t)n * PER_ROI + half * HALF_OUT);
    o4[tid] = reinterpret_cast<const float4*>(s)[tid];
}

extern "C" void kernel_launch(void* const* d_in, const int* in_sizes, int n_in,
                              void* d_out, int out_size)
{
    const float* feat = (const float*)d_in[0];   // (B, 64, 38, 38)
    const float* rois = (const float*)d_in[1];   // (B, Nb, 4)
    float* out = (float*)d_out;

    const int B = in_sizes[0] / (FC * PLANE);    // 4
    const int n_roi = in_sizes[1] / 4;           // 11616
    const int nb = n_roi / B;                    // 2904

    dim3 tgrid((PLANE + 31) / 32, FC / 32, B);
    dim3 tblock(32, 8);
    nchw2nhwc_kernel<<<tgrid, tblock>>>(feat);

    const int n_items = n_roi * NPIX;            // 569184
    precompute_kernel<<<(n_items + 255) / 256, 256>>>(rois, n_items);

    dim3 grid(n_roi, 2);
    dim3 block(8, 49);
    roialign_nhwc_kernel<<<grid, block>>>(out, nb);
}

// round 8
// speedup vs baseline: 1.2378x; 1.2378x over previous
#include <cuda_runtime.h>

// ROIAlign: features (4, 64, 38, 38) fp32, rois (4, 2904, 4) -> (11616, 64, 7, 7).
//
// R8 = R6 structure (NHWC gathers, conflict-free smem staging, one barrier,
// coalesced float4 flush) with issue/ALU load halved:
//   - ONE block per ROI; each thread handles 8 channels (c = 4cg, 4cg+32)
//     -> weight math executed in 12.25 warps/ROI instead of 24.5
//   - weight computation simplified using the provable coord range [0,38]
//     (rois in [0,37], w = max(dx,1) -> x >= 0 always, OOB only on the right)

#define FB 4
#define FH 38
#define FW 38
#define FC 64
#define OS 7
#define PLANE (FH * FW)               // 1444
#define PER_ROI (FC * OS * OS)        // 3136
#define NPIX (OS * OS)                // 49

__device__ float g_nhwc[FB * PLANE * FC];   // [b][h][w][c], 1.48 MB

// ---------------- kernel 1: NCHW -> NHWC tiled transpose ----------------
__global__ __launch_bounds__(256)
void nchw2nhwc_kernel(const float* __restrict__ feat)
{
    __shared__ float tile[32][33];
    const int b = blockIdx.z;
    const int hw0 = blockIdx.x * 32;
    const int c0 = blockIdx.y * 32;

    const float* in = feat + (size_t)b * FC * PLANE;
    float* outp = g_nhwc + (size_t)b * PLANE * FC;

    const int tx = threadIdx.x;
    const int ty = threadIdx.y;

#pragma unroll
    for (int i = 0; i < 32; i += 8) {
        const int c = c0 + ty + i;
        const int hw = hw0 + tx;
        if (hw < PLANE)
            tile[ty + i][tx] = in[c * PLANE + hw];
    }
    __syncthreads();
#pragma unroll
    for (int i = 0; i < 32; i += 8) {
        const int hw = hw0 + ty + i;
        const int c = c0 + tx;
        if (hw < PLANE)
            outp[hw * FC + c] = tile[tx][ty + i];
    }
}

// ---------------- kernel 2: ROIAlign, one block per ROI ----------------
// blockDim = (8, 49) = 392 threads.
//   threadIdx.x = cg in [0,8): channels 4cg..4cg+3 and 4cg+32..4cg+35
//   threadIdx.y = p in [0,49): output pixel
__global__ __launch_bounds__(392, 4)
void roialign_nhwc_kernel(const float* __restrict__ rois,
                          float* __restrict__ out,
                          int nb_per_batch)
{
    __shared__ float s[PER_ROI];         // staging: [c*49 + p], 12.5 KB

    const int n = blockIdx.x;
    const int cg = threadIdx.x;          // 0..7
    const int p = threadIdx.y;           // 0..48
    const int tid = cg + 8 * p;          // 0..391
    const int b = n / nb_per_batch;

    // ---- bilinear weights/offsets (coords provably in [0,38]) ----
    const float4 r = __ldg(reinterpret_cast<const float4*>(rois) + n);
    const float rw = fmaxf(r.z - r.x, 1.0f);
    const float rh = fmaxf(r.w - r.y, 1.0f);

    const int ox = p % OS;
    const int oy = p / OS;

    const float x = fmaf((float)ox * (1.0f / 6.0f), rw, r.x);
    const float y = fmaf((float)oy * (1.0f / 6.0f), rh, r.y);

    const float x0f = floorf(x);
    const float y0f = floorf(y);
    const float fx = x - x0f;
    const float fy = y - y0f;

    const int x0 = (int)x0f;             // in [0, 38]
    const int y0 = (int)y0f;

    const float wx1 = (x0 <= FW - 2) ? fx : 0.0f;
    const float wx0 = (x0 <= FW - 1) ? 1.0f - fx : 0.0f;
    const float wy1 = (y0 <= FH - 2) ? fy : 0.0f;
    const float wy0 = (y0 <= FH - 1) ? 1.0f - fy : 0.0f;

    const int xi0 = min(x0, FW - 1);
    const int xi1 = min(x0 + 1, FW - 1);
    const int yi0 = min(y0, FH - 1);
    const int yi1 = min(y0 + 1, FH - 1);

    const float w00 = wx0 * wy0;
    const float w01 = wx1 * wy0;
    const float w10 = wx0 * wy1;
    const float w11 = wx1 * wy1;

    const int o00 = (yi0 * FW + xi0) * FC;
    const int o01 = (yi0 * FW + xi1) * FC;
    const int o10 = (yi1 * FW + xi0) * FC;
    const int o11 = (yi1 * FW + xi1) * FC;

    const float* __restrict__ fb = g_nhwc + (size_t)b * PLANE * FC + 4 * cg;

    // ---- wave 1: channels [4cg, 4cg+4) ----
    {
        const float4 v00 = *reinterpret_cast<const float4*>(fb + o00);
        const float4 v01 = *reinterpret_cast<const float4*>(fb + o01);
        const float4 v10 = *reinterpret_cast<const float4*>(fb + o10);
        const float4 v11 = *reinterpret_cast<const float4*>(fb + o11);

        float4 a;
        a.x = fmaf(w00, v00.x, fmaf(w01, v01.x, fmaf(w10, v10.x, w11 * v11.x)));
        a.y = fmaf(w00, v00.y, fmaf(w01, v01.y, fmaf(w10, v10.y, w11 * v11.y)));
        a.z = fmaf(w00, v00.z, fmaf(w01, v01.z, fmaf(w10, v10.z, w11 * v11.z)));
        a.w = fmaf(w00, v00.w, fmaf(w01, v01.w, fmaf(w10, v10.w, w11 * v11.w)));

        const int cl = 4 * cg;
        s[(cl + 0) * NPIX + p] = a.x;    // conflict-free banking
        s[(cl + 1) * NPIX + p] = a.y;
        s[(cl + 2) * NPIX + p] = a.z;
        s[(cl + 3) * NPIX + p] = a.w;
    }

    // ---- wave 2: channels [4cg+32, 4cg+36) ----
    {
        const float4 v00 = *reinterpret_cast<const float4*>(fb + o00 + 32);
        const float4 v01 = *reinterpret_cast<const float4*>(fb + o01 + 32);
        const float4 v10 = *reinterpret_cast<const float4*>(fb + o10 + 32);
        const float4 v11 = *reinterpret_cast<const float4*>(fb + o11 + 32);

        float4 a;
        a.x = fmaf(w00, v00.x, fmaf(w01, v01.x, fmaf(w10, v10.x, w11 * v11.x)));
        a.y = fmaf(w00, v00.y, fmaf(w01, v01.y, fmaf(w10, v10.y, w11 * v11.y)));
        a.z = fmaf(w00, v00.z, fmaf(w01, v01.z, fmaf(w10, v10.z, w11 * v11.z)));
        a.w = fmaf(w00, v00.w, fmaf(w01, v01.w, fmaf(w10, v10.w, w11 * v11.w)));

        const int cl = 4 * cg + 32;
        s[(cl + 0) * NPIX + p] = a.x;
        s[(cl + 1) * NPIX + p] = a.y;
        s[(cl + 2) * NPIX + p] = a.z;
        s[(cl + 3) * NPIX + p] = a.w;
    }

    __syncthreads();                     // the ONLY barrier

    // ---- flush: 784 coalesced float4 stores (2 per thread) ----
    float4* o4 = reinterpret_cast<float4*>(out + (size_t)n * PER_ROI);
    const float4* s4 = reinterpret_cast<const float4*>(s);
    o4[tid] = s4[tid];
    o4[tid + 392] = s4[tid + 392];
}

extern "C" void kernel_launch(void* const* d_in, const int* in_sizes, int n_in,
                              void* d_out, int out_size)
{
    const float* feat = (const float*)d_in[0];   // (B, 64, 38, 38)
    const float* rois = (const float*)d_in[1];   // (B, Nb, 4)
    float* out = (float*)d_out;

    const int B = in_sizes[0] / (FC * PLANE);    // 4
    const int n_roi = in_sizes[1] / 4;           // 11616
    const int nb = n_roi / B;                    // 2904

    dim3 tgrid((PLANE + 31) / 32, FC / 32, B);
    dim3 tblock(32, 8);
    nchw2nhwc_kernel<<<tgrid, tblock>>>(feat);

    dim3 block(8, 49);
    roialign_nhwc_kernel<<<n_roi, block>>>(rois, out, nb);
}